// round 1
// baseline (speedup 1.0000x reference)
#include <cuda_runtime.h>
#include <cuda_bf16.h>

#define NTHR 128

__device__ __forceinline__ float clip01(float v) { return fminf(fmaxf(v, 0.0f), 1.0f); }

__global__ __launch_bounds__(NTHR)
void gotd_eval_kernel(const float* __restrict__ G,   // gaze heatmaps   [n,64,64]
                      const float* __restrict__ H,   // head heatmaps   [n,64,64]
                      const float* __restrict__ C,   // connect heatmaps[n,64,64]
                      const float* __restrict__ W,   // watch_outside   [n]
                      float* __restrict__ out, int n)
{
    const int bq = blockIdx.x;
    if (bq >= n) return;
    const int t = threadIdx.x;
    const size_t base = (size_t)bq * 4096;

    const float4* h4 = reinterpret_cast<const float4*>(H + base);
    const float4* g4 = reinterpret_cast<const float4*>(G + base);

    __shared__ unsigned long long s_colmask, s_rowmask;
    __shared__ float s_wv[2][4];
    __shared__ int   s_wi[2][4];
    __shared__ float s_rmax[4];
    __shared__ int   s_box[4];
    __shared__ float s_gmax;
    __shared__ int   s_gidx;

    if (t == 0) { s_colmask = 0ull; s_rowmask = 0ull; }
    __syncthreads();

    // ---- Load head + gaze tiles, coalesced float4 (thread t owns float4 slots
    // j*128+t, i.e. elements idx=(j*128+t)*4+k; row=j*8+(t>>4); col=(t&15)*4+k) ----
    float4 hreg[8];
    float4 graw[8];
#pragma unroll
    for (int j = 0; j < 8; j++) hreg[j] = h4[j * 128 + t];
#pragma unroll
    for (int j = 0; j < 8; j++) graw[j] = g4[j * 128 + t];

    float hmax = -1.0f; int hidx = 0;
    float gmax = -1.0f; int gidx = 0;
    unsigned colnib = 0;                 // 4 column bits (cols fixed per thread)
    unsigned long long rowm = 0ull;

#pragma unroll
    for (int j = 0; j < 8; j++) {
        float v[4] = {hreg[j].x, hreg[j].y, hreg[j].z, hreg[j].w};
        bool any5 = false;
#pragma unroll
        for (int k = 0; k < 4; k++) {
            float hv = clip01(v[k]);
            v[k] = hv;
            int idx = (j * 128 + t) * 4 + k;
            if (hv > hmax) { hmax = hv; hidx = idx; }   // strict > : first-index argmax
            if (hv >= 0.5f) { colnib |= 1u << k; any5 = true; }
        }
        hreg[j] = make_float4(v[0], v[1], v[2], v[3]); // keep clipped tile in regs
        if (any5) rowm |= 1ull << (j * 8 + (t >> 4));
    }

#pragma unroll
    for (int j = 0; j < 8; j++) {
        float v[4] = {graw[j].x, graw[j].y, graw[j].z, graw[j].w};
#pragma unroll
        for (int k = 0; k < 4; k++) {
            float gv = clip01(v[k]);
            int idx = (j * 128 + t) * 4 + k;
            if (gv > gmax) { gmax = gv; gidx = idx; }
        }
    }

    if (colnib) atomicOr(&s_colmask, (unsigned long long)colnib << ((t & 15) * 4));
    if (rowm)   atomicOr(&s_rowmask, rowm);

    // ---- warp (val,idx) argmax reductions, min-idx tie-break ----
    const int wid = t >> 5, lane = t & 31;
#pragma unroll
    for (int o = 16; o; o >>= 1) {
        float hv2 = __shfl_down_sync(0xffffffffu, hmax, o);
        int   hi2 = __shfl_down_sync(0xffffffffu, hidx, o);
        if (hv2 > hmax || (hv2 == hmax && hi2 < hidx)) { hmax = hv2; hidx = hi2; }
        float gv2 = __shfl_down_sync(0xffffffffu, gmax, o);
        int   gi2 = __shfl_down_sync(0xffffffffu, gidx, o);
        if (gv2 > gmax || (gv2 == gmax && gi2 < gidx)) { gmax = gv2; gidx = gi2; }
    }
    if (lane == 0) {
        s_wv[0][wid] = hmax; s_wi[0][wid] = hidx;
        s_wv[1][wid] = gmax; s_wi[1][wid] = gidx;
    }
    __syncthreads();

    if (t == 0) {
        float hv2 = s_wv[0][0]; int hi2 = s_wi[0][0];
#pragma unroll
        for (int w = 1; w < 4; w++)
            if (s_wv[0][w] > hv2 || (s_wv[0][w] == hv2 && s_wi[0][w] < hi2)) { hv2 = s_wv[0][w]; hi2 = s_wi[0][w]; }
        float gv2 = s_wv[1][0]; int gi2 = s_wi[1][0];
#pragma unroll
        for (int w = 1; w < 4; w++)
            if (s_wv[1][w] > gv2 || (s_wv[1][w] == gv2 && s_wi[1][w] < gi2)) { gv2 = s_wv[1][w]; gi2 = s_wi[1][w]; }

        // ---- bbox from masks, fallback to head peak ----
        unsigned long long cm = s_colmask, rm = s_rowmask;
        int x1, x2, y1, y2;
        if (cm) {
            x1 = __ffsll((long long)cm) - 1;
            x2 = 64 - __clzll((long long)cm);
            y1 = __ffsll((long long)rm) - 1;
            y2 = 64 - __clzll((long long)rm);
        } else {
            int px = hi2 & 63, py = hi2 >> 6;
            x1 = px; x2 = px + 1; y1 = py; y2 = py + 1;
        }
        s_box[0] = x1; s_box[1] = x2; s_box[2] = y1; s_box[3] = y2;
        s_gmax = gv2; s_gidx = gi2;
    }
    __syncthreads();

    const int x1 = s_box[0], x2 = s_box[1], y1 = s_box[2], y2 = s_box[3];

    // ---- region max of clipped head over [y1,y2)x[x1,x2), register-resident ----
    float rmax = 0.0f;
    const int rbase = t >> 4;
    const int cbase = (t & 15) * 4;
#pragma unroll
    for (int j = 0; j < 8; j++) {
        int row = j * 8 + rbase;
        if (row >= y1 && row < y2) {
            float v[4] = {hreg[j].x, hreg[j].y, hreg[j].z, hreg[j].w};
#pragma unroll
            for (int k = 0; k < 4; k++) {
                int col = cbase + k;
                if (col >= x1 && col < x2) rmax = fmaxf(rmax, v[k]);
            }
        }
    }
#pragma unroll
    for (int o = 16; o; o >>= 1) rmax = fmaxf(rmax, __shfl_down_sync(0xffffffffu, rmax, o));
    if (lane == 0) s_rmax[wid] = rmax;
    __syncthreads();

    // ---- scalar epilogue: line-sample connect heatmap (only 10 pixels!) ----
    if (t == 0) {
        float conf_head = fmaxf(fmaxf(s_rmax[0], s_rmax[1]), fmaxf(s_rmax[2], s_rmax[3]));
        float conf_gaze = s_gmax;
        int gi = s_gidx;
        float gpx = fminf(fmaxf((float)(gi & 63), 0.0f), 63.0f);
        float gpy = fminf(fmaxf((float)(gi >> 6), 0.0f), 63.0f);
        float cx = (float)(x1 + x2) * 0.5f;
        float cy = (float)(y1 + y2) * 0.5f;
        // jnp.round == round-half-to-even == rintf (cx/cy hit .5 exactly!)
        float hcx = fminf(fmaxf(rintf(cx), 0.0f), 63.0f);
        float hcy = fminf(fmaxf(rintf(cy), 0.0f), 63.0f);
        float dx = gpx - hcx, dy = gpy - hcy;
        float stx = dx / 9.0f, sty = dy / 9.0f;   // linspace step, num=10
        const float* c = C + base;
        float sum = 0.0f;
#pragma unroll
        for (int i = 0; i < 10; i++) {
            int xi = (int)rintf(hcx + (float)i * stx);
            int yi = (int)rintf(hcy + (float)i * sty);
            sum += clip01(__ldg(c + yi * 64 + xi));
        }
        float norm = sqrtf(dx * dx + dy * dy);
        float dp = fminf(32.0f / norm - 1.0f, 0.0f);  // norm==0 -> +inf -> 0
        float score = sum / 10.0f + dp;
        float watch = W[bq];
        float r = (watch > 0.5f)
                ? (conf_head + (1.0f - conf_gaze) - score)
                : (conf_head + conf_gaze + score);
        out[bq] = r / 3.0f;
    }
}

extern "C" void kernel_launch(void* const* d_in, const int* in_sizes, int n_in,
                              void* d_out, int out_size) {
    const float* G = (const float*)d_in[0];  // pred_gaze_heatmap
    const float* H = (const float*)d_in[1];  // pred_head_heatmap
    const float* C = (const float*)d_in[2];  // pred_connect_heatmap
    const float* W = (const float*)d_in[3];  // pred_gaze_watch_outside
    float* out = (float*)d_out;
    int n = in_sizes[3];                     // B*Q = 8192
    gotd_eval_kernel<<<n, NTHR>>>(G, H, C, W, out, n);
}

// round 2
// speedup vs baseline: 1.0040x; 1.0040x over previous
#include <cuda_runtime.h>
#include <cuda_bf16.h>

#define NTHR 128

__device__ __forceinline__ float clip01(float v) { return fminf(fmaxf(v, 0.0f), 1.0f); }

__global__ __launch_bounds__(NTHR)
void gotd_eval_kernel(const float* __restrict__ G,   // gaze heatmaps   [n,64,64]
                      const float* __restrict__ H,   // head heatmaps   [n,64,64]
                      const float* __restrict__ C,   // connect heatmaps[n,64,64]
                      const float* __restrict__ W,   // watch_outside   [n]
                      float* __restrict__ out, int n)
{
    const int bq = blockIdx.x;
    if (bq >= n) return;
    const int t = threadIdx.x;
    const size_t base = (size_t)bq * 4096;

    const float4* h4 = reinterpret_cast<const float4*>(H + base);
    const float4* g4 = reinterpret_cast<const float4*>(G + base);

    __shared__ unsigned long long s_colmask, s_rowmask;
    __shared__ float s_hv[4];
    __shared__ float s_gv[4];
    __shared__ int   s_gi[4];
    __shared__ float s_pv[4];
    __shared__ int   s_pi[4];

    if (t == 0) { s_colmask = 0ull; s_rowmask = 0ull; }
    __syncthreads();

    // Front-batched coalesced loads: thread t owns float4 slots j*128+t,
    // i.e. elements idx=(j*128+t)*4+k; row=j*8+(t>>4); col=(t&15)*4+k.
    float4 hreg[8];
    float4 greg[8];
#pragma unroll
    for (int j = 0; j < 8; j++) hreg[j] = h4[j * 128 + t];
#pragma unroll
    for (int j = 0; j < 8; j++) greg[j] = g4[j * 128 + t];

    // ---- head: ONLY max value + >=0.5 masks (no index tracking, no clip:
    //      conf_head = clip01(max) since clip is monotone; x>=0.5 <=> clip(x)>=0.5) ----
    float hmax = -1e30f;
    unsigned colnib = 0;
    unsigned long long rowm = 0ull;
#pragma unroll
    for (int j = 0; j < 8; j++) {
        float v[4] = {hreg[j].x, hreg[j].y, hreg[j].z, hreg[j].w};
        bool any5 = false;
#pragma unroll
        for (int k = 0; k < 4; k++) {
            hmax = fmaxf(hmax, v[k]);
            if (v[k] >= 0.5f) { colnib |= 1u << k; any5 = true; }
        }
        if (any5) rowm |= 1ull << (j * 8 + (t >> 4));
    }

    // ---- gaze: clipped (val, idx) argmax, strict > = first-index semantics ----
    float gmax = -1.0f; int gidx = 0;
#pragma unroll
    for (int j = 0; j < 8; j++) {
        float v[4] = {greg[j].x, greg[j].y, greg[j].z, greg[j].w};
#pragma unroll
        for (int k = 0; k < 4; k++) {
            float gv = clip01(v[k]);
            int idx = (j * 128 + t) * 4 + k;
            if (gv > gmax) { gmax = gv; gidx = idx; }
        }
    }

    if (colnib) atomicOr(&s_colmask, (unsigned long long)colnib << ((t & 15) * 4));
    if (rowm)   atomicOr(&s_rowmask, rowm);

    const int wid = t >> 5, lane = t & 31;
#pragma unroll
    for (int o = 16; o; o >>= 1) {
        hmax = fmaxf(hmax, __shfl_down_sync(0xffffffffu, hmax, o));
        float gv2 = __shfl_down_sync(0xffffffffu, gmax, o);
        int   gi2 = __shfl_down_sync(0xffffffffu, gidx, o);
        if (gv2 > gmax || (gv2 == gmax && gi2 < gidx)) { gmax = gv2; gidx = gi2; }
    }
    if (lane == 0) { s_hv[wid] = hmax; s_gv[wid] = gmax; s_gi[wid] = gidx; }
    __syncthreads();

    // ---- rare fallback: no head pixel >= 0.5 -> need head argmax index (peak box).
    //      Block-uniform branch; essentially never taken for uniform inputs. ----
    if (s_colmask == 0ull) {
        float pv = -1e30f; int pi = 0;
#pragma unroll
        for (int j = 0; j < 8; j++) {
            float4 hv4 = h4[j * 128 + t];   // reload (hits L2/L1)
            float v[4] = {hv4.x, hv4.y, hv4.z, hv4.w};
#pragma unroll
            for (int k = 0; k < 4; k++) {
                float hv = clip01(v[k]);
                int idx = (j * 128 + t) * 4 + k;
                if (hv > pv) { pv = hv; pi = idx; }
            }
        }
#pragma unroll
        for (int o = 16; o; o >>= 1) {
            float v2 = __shfl_down_sync(0xffffffffu, pv, o);
            int   i2 = __shfl_down_sync(0xffffffffu, pi, o);
            if (v2 > pv || (v2 == pv && i2 < pi)) { pv = v2; pi = i2; }
        }
        if (lane == 0) { s_pv[wid] = pv; s_pi[wid] = pi; }
        __syncthreads();
    }

    // ---- scalar epilogue ----
    if (t == 0) {
        float conf_head = clip01(fmaxf(fmaxf(s_hv[0], s_hv[1]), fmaxf(s_hv[2], s_hv[3])));

        float gv = s_gv[0]; int gi = s_gi[0];
#pragma unroll
        for (int w = 1; w < 4; w++)
            if (s_gv[w] > gv || (s_gv[w] == gv && s_gi[w] < gi)) { gv = s_gv[w]; gi = s_gi[w]; }
        float conf_gaze = gv;

        unsigned long long cm = s_colmask, rm = s_rowmask;
        int x1, x2, y1, y2;
        if (cm) {
            x1 = __ffsll((long long)cm) - 1;
            x2 = 64 - __clzll((long long)cm);
            y1 = __ffsll((long long)rm) - 1;
            y2 = 64 - __clzll((long long)rm);
        } else {
            float pv = s_pv[0]; int pi = s_pi[0];
#pragma unroll
            for (int w = 1; w < 4; w++)
                if (s_pv[w] > pv || (s_pv[w] == pv && s_pi[w] < pi)) { pv = s_pv[w]; pi = s_pi[w]; }
            int px = pi & 63, py = pi >> 6;
            x1 = px; x2 = px + 1; y1 = py; y2 = py + 1;
        }

        float gpx = fminf(fmaxf((float)(gi & 63), 0.0f), 63.0f);
        float gpy = fminf(fmaxf((float)(gi >> 6), 0.0f), 63.0f);
        float cx = (float)(x1 + x2) * 0.5f;
        float cy = (float)(y1 + y2) * 0.5f;
        // jnp.round == round-half-to-even == rintf (cx/cy hit .5 exactly)
        float hcx = fminf(fmaxf(rintf(cx), 0.0f), 63.0f);
        float hcy = fminf(fmaxf(rintf(cy), 0.0f), 63.0f);
        float dx = gpx - hcx, dy = gpy - hcy;
        float stx = dx / 9.0f, sty = dy / 9.0f;   // linspace step, num=10
        const float* c = C + base;
        float sum = 0.0f;
#pragma unroll
        for (int i = 0; i < 10; i++) {
            int xi = (int)rintf(hcx + (float)i * stx);
            int yi = (int)rintf(hcy + (float)i * sty);
            sum += clip01(__ldg(c + yi * 64 + xi));
        }
        float norm = sqrtf(dx * dx + dy * dy);
        float dp = fminf(32.0f / norm - 1.0f, 0.0f);  // norm==0 -> +inf -> 0
        float score = sum / 10.0f + dp;
        float watch = W[bq];
        float r = (watch > 0.5f)
                ? (conf_head + (1.0f - conf_gaze) - score)
                : (conf_head + conf_gaze + score);
        out[bq] = r / 3.0f;
    }
}

extern "C" void kernel_launch(void* const* d_in, const int* in_sizes, int n_in,
                              void* d_out, int out_size) {
    const float* G = (const float*)d_in[0];  // pred_gaze_heatmap
    const float* H = (const float*)d_in[1];  // pred_head_heatmap
    const float* C = (const float*)d_in[2];  // pred_connect_heatmap
    const float* W = (const float*)d_in[3];  // pred_gaze_watch_outside
    float* out = (float*)d_out;
    int n = in_sizes[3];                     // B*Q = 8192
    gotd_eval_kernel<<<n, NTHR>>>(G, H, C, W, out, n);
}

// round 3
// speedup vs baseline: 1.5144x; 1.5084x over previous
#include <cuda_runtime.h>
#include <cuda_bf16.h>

#define WARPS_PER_BLOCK 8
#define NTHR (32 * WARPS_PER_BLOCK)

__device__ __forceinline__ float clip01(float v) { return fminf(fmaxf(v, 0.0f), 1.0f); }

__global__ __launch_bounds__(NTHR, 4)
void gotd_eval_kernel(const float* __restrict__ G,   // gaze heatmaps   [n,64,64]
                      const float* __restrict__ H,   // head heatmaps   [n,64,64]
                      const float* __restrict__ C,   // connect heatmaps[n,64,64]
                      const float* __restrict__ W,   // watch_outside   [n]
                      float* __restrict__ out, int n)
{
    const int warp = threadIdx.x >> 5;
    const int lane = threadIdx.x & 31;
    const int bq = blockIdx.x * WARPS_PER_BLOCK + warp;
    if (bq >= n) return;

    const size_t base = (size_t)bq * 4096;
    const float4* h4 = reinterpret_cast<const float4*>(H + base);
    const float4* g4 = reinterpret_cast<const float4*>(G + base);

    // Per-lane layout: float4 slot s = m*32 + lane (m = 0..31);
    // element idx = s*4+k; row = s>>4 = 2*m + (lane>>4); col = (lane&15)*4 + k.
    float hmax = -1e30f;
    unsigned colnib = 0;              // 4 col bits (cols fixed per lane)
    unsigned rml = 0, rmh = 0;        // row mask lo/hi
    float gmax = -1.0f; int gidx = 0;

    // ---- head: max + >=0.5 masks only (conf_head = clip01(max); clip monotone) ----
#pragma unroll
    for (int b = 0; b < 4; b++) {
        float4 v[8];
#pragma unroll
        for (int i = 0; i < 8; i++) v[i] = h4[(b * 8 + i) * 32 + lane];
#pragma unroll
        for (int i = 0; i < 8; i++) {
            const int m = b * 8 + i;
            float a[4] = {v[i].x, v[i].y, v[i].z, v[i].w};
            bool any5 = false;
#pragma unroll
            for (int k = 0; k < 4; k++) {
                hmax = fmaxf(hmax, a[k]);
                if (a[k] >= 0.5f) { colnib |= 1u << k; any5 = true; }
            }
            if (any5) {
                int row = 2 * m + (lane >> 4);
                if (row < 32) rml |= 1u << row; else rmh |= 1u << (row - 32);
            }
        }
    }

    // ---- gaze: clipped (val, idx) argmax, strict > = first-index semantics ----
#pragma unroll
    for (int b = 0; b < 4; b++) {
        float4 v[8];
#pragma unroll
        for (int i = 0; i < 8; i++) v[i] = g4[(b * 8 + i) * 32 + lane];
#pragma unroll
        for (int i = 0; i < 8; i++) {
            const int m = b * 8 + i;
            float a[4] = {v[i].x, v[i].y, v[i].z, v[i].w};
#pragma unroll
            for (int k = 0; k < 4; k++) {
                float gv = clip01(a[k]);
                int idx = (m * 32 + lane) * 4 + k;
                if (gv > gmax) { gmax = gv; gidx = idx; }
            }
        }
    }

    // ---- warp-wide masks via REDUX (uniform result in all lanes) ----
    const unsigned c15 = lane & 15;
    unsigned mcl = (c15 < 8)  ? (colnib << (c15 * 4))       : 0u;
    unsigned mch = (c15 >= 8) ? (colnib << ((c15 - 8) * 4)) : 0u;
    const unsigned cl = __reduce_or_sync(0xffffffffu, mcl);
    const unsigned ch = __reduce_or_sync(0xffffffffu, mch);
    const unsigned rl = __reduce_or_sync(0xffffffffu, rml);
    const unsigned rh = __reduce_or_sync(0xffffffffu, rmh);

    // ---- butterfly reductions: every lane ends with the warp result ----
#pragma unroll
    for (int o = 16; o; o >>= 1) {
        hmax = fmaxf(hmax, __shfl_xor_sync(0xffffffffu, hmax, o));
        float gv2 = __shfl_xor_sync(0xffffffffu, gmax, o);
        int   gi2 = __shfl_xor_sync(0xffffffffu, gidx, o);
        if (gv2 > gmax || (gv2 == gmax && gi2 < gidx)) { gmax = gv2; gidx = gi2; }
    }

    // ---- bbox (rare fallback: no pixel >= 0.5 -> head argmax peak, warp-uniform) ----
    int x1, x2, y1, y2;
    if ((cl | ch) != 0u) {
        unsigned long long cm = ((unsigned long long)ch << 32) | cl;
        unsigned long long rm = ((unsigned long long)rh << 32) | rl;
        x1 = __ffsll((long long)cm) - 1;
        x2 = 64 - __clzll((long long)cm);
        y1 = __ffsll((long long)rm) - 1;
        y2 = 64 - __clzll((long long)rm);
    } else {
        float pv = -1e30f; int pi = 0;
#pragma unroll 4
        for (int m = 0; m < 32; m++) {
            float4 v = h4[m * 32 + lane];          // reload (L2-hot)
            float a[4] = {v.x, v.y, v.z, v.w};
#pragma unroll
            for (int k = 0; k < 4; k++) {
                float hv = clip01(a[k]);
                int idx = (m * 32 + lane) * 4 + k;
                if (hv > pv) { pv = hv; pi = idx; }
            }
        }
#pragma unroll
        for (int o = 16; o; o >>= 1) {
            float v2 = __shfl_xor_sync(0xffffffffu, pv, o);
            int   i2 = __shfl_xor_sync(0xffffffffu, pi, o);
            if (v2 > pv || (v2 == pv && i2 < pi)) { pv = v2; pi = i2; }
        }
        int px = pi & 63, py = pi >> 6;
        x1 = px; x2 = px + 1; y1 = py; y2 = py + 1;
    }

    // ---- epilogue (warp-uniform math; 10 connect samples spread over lanes 0-9) ----
    const float conf_head = clip01(hmax);
    const float conf_gaze = gmax;
    const float gpx = fminf(fmaxf((float)(gidx & 63), 0.0f), 63.0f);
    const float gpy = fminf(fmaxf((float)(gidx >> 6), 0.0f), 63.0f);
    const float cx = (float)(x1 + x2) * 0.5f;
    const float cy = (float)(y1 + y2) * 0.5f;
    // jnp.round == round-half-to-even == rintf (cx/cy hit .5 exactly)
    const float hcx = fminf(fmaxf(rintf(cx), 0.0f), 63.0f);
    const float hcy = fminf(fmaxf(rintf(cy), 0.0f), 63.0f);
    const float dx = gpx - hcx, dy = gpy - hcy;
    const float stx = dx / 9.0f, sty = dy / 9.0f;   // linspace step, num=10

    float samp = 0.0f;
    if (lane < 10) {
        int xi = (int)rintf(hcx + (float)lane * stx);
        int yi = (int)rintf(hcy + (float)lane * sty);
        samp = clip01(__ldg(C + base + yi * 64 + xi));
    }
#pragma unroll
    for (int o = 16; o; o >>= 1) samp += __shfl_xor_sync(0xffffffffu, samp, o);

    if (lane == 0) {
        float norm = sqrtf(dx * dx + dy * dy);
        float dp = fminf(32.0f / norm - 1.0f, 0.0f);  // norm==0 -> +inf -> 0
        float score = samp / 10.0f + dp;
        float watch = W[bq];
        float r = (watch > 0.5f)
                ? (conf_head + (1.0f - conf_gaze) - score)
                : (conf_head + conf_gaze + score);
        out[bq] = r / 3.0f;
    }
}

extern "C" void kernel_launch(void* const* d_in, const int* in_sizes, int n_in,
                              void* d_out, int out_size) {
    const float* G = (const float*)d_in[0];  // pred_gaze_heatmap
    const float* H = (const float*)d_in[1];  // pred_head_heatmap
    const float* C = (const float*)d_in[2];  // pred_connect_heatmap
    const float* W = (const float*)d_in[3];  // pred_gaze_watch_outside
    float* out = (float*)d_out;
    int n = in_sizes[3];                     // B*Q = 8192
    int grid = (n + WARPS_PER_BLOCK - 1) / WARPS_PER_BLOCK;
    gotd_eval_kernel<<<grid, NTHR>>>(G, H, C, W, out, n);
}